// round 7
// baseline (speedup 1.0000x reference)
#include <cuda_runtime.h>
#include <stdint.h>

// IN:  x (4, 64, 224, 224) fp32
// OUT: (4, 576, 223*223) fp32, plane ck = bc*9 + ki*3 + kj
// out[ck, oh*223+ow] = x[bc, oh+ki-1, ow+kj-1] (0 if OOB)
#define OSP   49729u      // 223*223
#define ISTR  50176u      // 224*224

// Block = (8-row output group, bc). 9 warps = 9 (ki,kj) planes.
// Stages 11 padded input rows as 4 pre-shifted copies:
//   sb[d][sr][k] = row_padded[k + d]   (row_padded: 4 zero | 224 data | 4 zero)
// so every output float4 is ONE aligned LDS.128 (no second load, no select).
__global__ void __launch_bounds__(288) unfold_shift(const float* __restrict__ x,
                                                    float* __restrict__ out) {
    __shared__ __align__(16) float sb[4][11][232];   // 40.8 KB
    unsigned g8  = blockIdx.x * 8u;                  // first oh of chunk
    unsigned bc  = blockIdx.y;
    unsigned tid = threadIdx.x;
    unsigned w = tid >> 5, lane = tid & 31u;

    // ---- stage: thread owns padded column c for all 11 rows ----
    if (tid < 232u) {
        unsigned c = tid;
        const float* xb = x + (size_t)bc * ISTR;
        bool in_col = (c >= 4u && c < 228u);
#pragma unroll
        for (unsigned sr = 0; sr < 11u; ++sr) {
            int ih = (int)g8 - 1 + (int)sr;
            float v = 0.0f;
            if (in_col && (unsigned)ih < 224u)
                v = __ldg(xb + (size_t)ih * 224u + (c - 4u));
            sb[0][sr][c] = v;
            if (c >= 1u) sb[1][sr][c - 1u] = v;
            if (c >= 2u) sb[2][sr][c - 2u] = v;
            if (c >= 3u) sb[3][sr][c - 3u] = v;
        }
    }
    __syncthreads();

    unsigned ki = w / 3u;
    unsigned kj = w - 3u * ki;
    unsigned ck = bc * 9u + w;
    unsigned nrows = (g8 + 8u <= 223u) ? 8u : (223u - g8);   // 8, last chunk 7

    for (unsigned r = 0; r < nrows; ++r) {
        unsigned oh   = g8 + r;
        size_t   drow = (size_t)ck * OSP + (size_t)oh * 223u;
        unsigned lead = (4u - ((unsigned)drow & 3u)) & 3u;
        unsigned tail = 3u - lead;
        unsigned sr   = r + ki;
        unsigned off  = lead + kj + 3u;     // row_padded idx of first body float
        unsigned dlt  = off & 3u;
        unsigned jb   = off >> 2u;
        const float4* B = (const float4*)sb[dlt][sr];
        float4* dst4 = (float4*)(out + drow + lead);

        // 55 aligned float4: one LDS.128 + one STG.128 each
        for (unsigned j = lane; j < 55u; j += 32u) {
            __stcs(dst4 + j, B[jb + j]);    // B[jb+j] = row_padded[off+4j .. +3]
        }

        // straddle float4 across the row boundary (tail of oh + lead of oh+1)
        if (lane == 0u && tail != 0u && oh < 222u) {
            float vv[4];
#pragma unroll
            for (unsigned t = 0; t < 4u; ++t) {
                vv[t] = (t < tail) ? sb[0][sr][off + 220u + t]
                                   : sb[0][sr + 1u][(t - tail) + kj + 3u];
            }
            __stcs((float4*)(out + drow + lead + 220u),
                   make_float4(vv[0], vv[1], vv[2], vv[3]));
        }

        // plane-end tail scalars (oh == 222 only)
        if (oh == 222u && lane < tail) {
            __stcs(out + drow + lead + 220u + lane, sb[0][sr][off + 220u + lane]);
        }

        // plane-start head scalars (first row of plane only)
        if (g8 == 0u && r == 0u && lane < lead) {
            __stcs(out + drow + lane, sb[0][sr][lane + kj + 3u]);
        }
    }
}

extern "C" void kernel_launch(void* const* d_in, const int* in_sizes, int n_in,
                              void* d_out, int out_size) {
    const float* x = (const float*)d_in[0];
    float* out = (float*)d_out;
    dim3 grid(28, 256);   // 28 row-groups (27*8 + 7), 256 bc planes
    unfold_shift<<<grid, 288>>>(x, out);
}

// round 8
// speedup vs baseline: 1.1188x; 1.1188x over previous
#include <cuda_runtime.h>
#include <stdint.h>

// IN:  x (4, 64, 224, 224) fp32
// OUT: (4, 576, 223*223) fp32, plane ck = bc*9 + ki*3 + kj
// out[ck, oh*223+ow] = x[bc, oh+ki-1, ow+kj-1] (0 if OOB)
#define OSP   49729u      // 223*223
#define ISTR  50176u      // 224*224

// Block = (8-row output group, bc). 9 warps = 9 (ki,kj) planes.
// Stages 11 padded input rows P (4 zero | 224 | 4 zero) as TWO copies:
//   sb0[sr][k] = P[k],  sb1[sr][k] = P[k+1]
// Every output float4 then costs one aligned LDS.128 (dlt even via sb0/odd via
// sb1 when (off&3)<2) or two aligned LDS.64 (dlt 2/3) -- same crossbar bytes,
// no select ALU, half of round-6's LDS traffic.
__global__ void __launch_bounds__(288) unfold_s2(const float* __restrict__ x,
                                                 float* __restrict__ out) {
    __shared__ __align__(16) float sb0[11][232];
    __shared__ __align__(16) float sb1[11][232];
    unsigned g8  = blockIdx.x * 8u;            // first oh of chunk
    unsigned bc  = blockIdx.y;
    unsigned tid = threadIdx.x;
    unsigned w = tid >> 5, lane = tid & 31u;

    // ---- stage: thread owns padded column c across all 11 rows ----
    if (tid < 232u) {
        unsigned c = tid;
        const float* xb = x + (size_t)bc * ISTR;
        bool in_col = (c >= 4u && c < 228u);
#pragma unroll
        for (unsigned sr = 0; sr < 11u; ++sr) {
            int ih = (int)g8 - 1 + (int)sr;
            float v = 0.0f;
            if (in_col && (unsigned)ih < 224u)
                v = __ldg(xb + (size_t)ih * 224u + (c - 4u));
            sb0[sr][c] = v;
            if (c >= 1u) sb1[sr][c - 1u] = v;
            if (c == 231u) sb1[sr][231] = 0.0f;
        }
    }
    __syncthreads();

    unsigned ki = w / 3u;
    unsigned kj = w - 3u * ki;
    unsigned ck = bc * 9u + w;
    unsigned nrows = (g8 + 8u <= 223u) ? 8u : (223u - g8);   // 8, last 7

    for (unsigned r = 0; r < nrows; ++r) {
        unsigned oh   = g8 + r;
        size_t   drow = (size_t)ck * OSP + (size_t)oh * 223u;
        unsigned lead = (4u - ((unsigned)drow & 3u)) & 3u;
        unsigned tail = 3u - lead;
        unsigned sr   = r + ki;
        unsigned off  = lead + kj + 3u;     // P idx of first body float (3..8)
        unsigned dlt  = off & 3u;
        float4* dst4 = (float4*)(out + drow + lead);

        // 55 aligned float4 stores; value = P[off+4j .. off+4j+3]
        switch (dlt) {
        case 0: {   // off in {4,8}: LDS.128 from sb0
            const float4* B = (const float4*)sb0[sr];
            unsigned jb = off >> 2u;
            for (unsigned j = lane; j < 55u; j += 32u)
                __stcs(dst4 + j, B[jb + j]);
        } break;
        case 1: {   // off==5: P[off+4j] = sb1[off-1+4j] -> LDS.128 from sb1
            const float4* B = (const float4*)sb1[sr];
            unsigned jb = (off - 1u) >> 2u;
            for (unsigned j = lane; j < 55u; j += 32u)
                __stcs(dst4 + j, B[jb + j]);
        } break;
        case 2: {   // off==6: two LDS.64 from sb0 (8B aligned)
            const float2* H = (const float2*)sb0[sr];
            unsigned hb = off >> 1u;
            for (unsigned j = lane; j < 55u; j += 32u) {
                float2 a = H[hb + 2u * j];
                float2 b = H[hb + 2u * j + 1u];
                __stcs(dst4 + j, make_float4(a.x, a.y, b.x, b.y));
            }
        } break;
        default: {  // off in {3,7}: two LDS.64 from sb1
            const float2* H = (const float2*)sb1[sr];
            unsigned hb = (off - 1u) >> 1u;
            for (unsigned j = lane; j < 55u; j += 32u) {
                float2 a = H[hb + 2u * j];
                float2 b = H[hb + 2u * j + 1u];
                __stcs(dst4 + j, make_float4(a.x, a.y, b.x, b.y));
            }
        } break;
        }

        // straddle float4 across the row boundary (tail of oh + lead of oh+1)
        if (lane == 0u && tail != 0u && oh < 222u) {
            float vv[4];
#pragma unroll
            for (unsigned t = 0; t < 4u; ++t) {
                vv[t] = (t < tail) ? sb0[sr][off + 220u + t]
                                   : sb0[sr + 1u][(t - tail) + kj + 3u];
            }
            __stcs((float4*)(out + drow + lead + 220u),
                   make_float4(vv[0], vv[1], vv[2], vv[3]));
        }

        // plane-end tail scalars (oh == 222 only)
        if (oh == 222u && lane < tail) {
            __stcs(out + drow + lead + 220u + lane, sb0[sr][off + 220u + lane]);
        }

        // plane-start head scalars (first row of plane only)
        if (g8 == 0u && r == 0u && lane < lead) {
            __stcs(out + drow + lane, sb0[sr][lane + kj + 3u]);
        }
    }
}

extern "C" void kernel_launch(void* const* d_in, const int* in_sizes, int n_in,
                              void* d_out, int out_size) {
    const float* x = (const float*)d_in[0];
    float* out = (float*)d_out;
    dim3 grid(28, 256);   // 28 row-groups (27*8 + 7), 256 bc planes
    unfold_s2<<<grid, 288>>>(x, out);
}

// round 9
// speedup vs baseline: 1.3089x; 1.1699x over previous
#include <cuda_runtime.h>
#include <stdint.h>

// IN:  x (4, 64, 224, 224) fp32
// OUT: (4, 576, 223*223) fp32, plane ck = bc*9 + ki*3 + kj
// out[ck, oh*223+ow] = x[bc, oh+ki-1, ow+kj-1] (0 if OOB)
#define OSP   49729u      // 223*223
#define ISTR  50176u      // 224*224

__device__ __forceinline__ float4 sel4(unsigned dlt, float4 a, float4 b) {
    switch (dlt) {
      case 0:  return a;
      case 1:  return make_float4(a.y, a.z, a.w, b.x);
      case 2:  return make_float4(a.z, a.w, b.x, b.y);
      default: return make_float4(a.w, b.x, b.y, b.z);
    }
}

template <int NR>
__device__ __forceinline__ void do_rows(const float (*sbuf)[232],
                                        float* __restrict__ out,
                                        unsigned g8, unsigned ck,
                                        unsigned ki, unsigned kj, unsigned lane) {
#pragma unroll
    for (int r = 0; r < NR; ++r) {
        unsigned oh   = g8 + (unsigned)r;
        size_t   drow = (size_t)ck * OSP + (size_t)oh * 223u;
        unsigned lead = (4u - ((unsigned)drow & 3u)) & 3u;
        unsigned tail = 3u - lead;
        unsigned sr   = (unsigned)r + ki;
        unsigned off  = lead + kj + 3u;     // padded-row idx of first body float
        unsigned dlt  = off & 3u;
        unsigned jb   = off >> 2u;
        const float4* sm4 = (const float4*)sbuf[sr];
        float4* dst4 = (float4*)(out + drow + lead);

        // 55 aligned float4 stores, flattened (lane and lane+32)
        {
            float4 a0 = sm4[jb + lane];
            float4 b0 = sm4[jb + lane + 1u];
            float4 a1, b1;
            if (lane < 23u) {
                a1 = sm4[jb + lane + 32u];
                b1 = sm4[jb + lane + 33u];
            }
            __stcs(dst4 + lane, sel4(dlt, a0, b0));
            if (lane < 23u)
                __stcs(dst4 + lane + 32u, sel4(dlt, a1, b1));
        }

        // straddle float4 across row boundary (tail of oh + lead of oh+1)
        if (lane == 0u && tail != 0u && oh < 222u) {
            float vv[4];
#pragma unroll
            for (unsigned t = 0; t < 4u; ++t) {
                vv[t] = (t < tail) ? sbuf[sr][off + 220u + t]
                                   : sbuf[sr + 1u][(t - tail) + kj + 3u];
            }
            __stcs((float4*)(out + drow + lead + 220u),
                   make_float4(vv[0], vv[1], vv[2], vv[3]));
        }

        // plane-end tail scalars (oh == 222 only)
        if (oh == 222u && lane < tail) {
            __stcs(out + drow + lead + 220u + lane, sbuf[sr][off + 220u + lane]);
        }

        // plane-start head scalars (first row of plane only)
        if (g8 == 0u && r == 0 && lane < lead) {
            __stcs(out + drow + lane, sbuf[sr][lane + kj + 3u]);
        }
    }
}

// Block = (8-row output group, bc). 9 warps = 9 (ki,kj) planes.
// Stages input rows ih in [g8-1, g8+9] (11 padded rows) via LDG.128/STS.128.
__global__ void __launch_bounds__(288) unfold_v9(const float* __restrict__ x,
                                                 float* __restrict__ out) {
    __shared__ __align__(16) float sbuf[11][232];  // 4 zero | 224 data | 4 zero
    unsigned g8  = blockIdx.x * 8u;
    unsigned bc  = blockIdx.y;
    unsigned tid = threadIdx.x;
    unsigned w = tid >> 5, lane = tid & 31u;

    // zero the 8 pad floats of each of the 11 rows (88 threads)
    if (tid < 88u) {
        unsigned sr = tid >> 3u, p = tid & 7u;
        sbuf[sr][p < 4u ? p : 224u + p] = 0.0f;
    }
    // vector staging: 11 rows x 56 float4, all 288 threads
    {
        const float4* xb4 = (const float4*)(x + (size_t)bc * ISTR);
        for (unsigned f = tid; f < 616u; f += 288u) {
            unsigned sr = f / 56u;
            unsigned q  = f - 56u * sr;
            int ih = (int)g8 - 1 + (int)sr;
            float4 v = make_float4(0.f, 0.f, 0.f, 0.f);
            if ((unsigned)ih < 224u) v = __ldg(xb4 + (unsigned)ih * 56u + q);
            *((float4*)&sbuf[sr][4] + q) = v;
        }
    }
    __syncthreads();

    unsigned ki = w / 3u;
    unsigned kj = w - 3u * ki;
    unsigned ck = bc * 9u + w;

    if (g8 != 216u) do_rows<8>(sbuf, out, g8, ck, ki, kj, lane);
    else            do_rows<7>(sbuf, out, g8, ck, ki, kj, lane);
}

extern "C" void kernel_launch(void* const* d_in, const int* in_sizes, int n_in,
                              void* d_out, int out_size) {
    const float* x = (const float*)d_in[0];
    float* out = (float*)d_out;
    dim3 grid(28, 256);   // 28 row-groups (27*8 + 7), 256 bc planes
    unfold_v9<<<grid, 288>>>(x, out);
}

// round 10
// speedup vs baseline: 1.3658x; 1.0434x over previous
#include <cuda_runtime.h>
#include <stdint.h>

// IN:  x (4, 64, 224, 224) fp32
// OUT: (4, 576, 223*223) fp32, plane ck = bc*9 + ki*3 + kj
// out[ck, oh*223+ow] = x[bc, oh+ki-1, ow+kj-1] (0 if OOB)
#define OSP   49729u      // 223*223
#define ISTR  50176u      // 224*224

// Block = (8-row output group, bc). 9 warps = 9 (ki,kj) planes.
// Round-6 row loop (low regs, high occ) + round-9 vector staging (LDG/STS.128).
__global__ void __launch_bounds__(288, 7) unfold_v10(const float* __restrict__ x,
                                                     float* __restrict__ out) {
    __shared__ __align__(16) float sbuf[11][232];  // 4 zero | 224 data | 4 zero
    unsigned g8  = blockIdx.x * 8u;
    unsigned bc  = blockIdx.y;
    unsigned tid = threadIdx.x;
    unsigned w = tid >> 5, lane = tid & 31u;

    // zero the 8 pad floats of each of the 11 rows (88 threads)
    if (tid < 88u) {
        unsigned sr = tid >> 3u, p = tid & 7u;
        sbuf[sr][p < 4u ? p : 224u + p] = 0.0f;
    }
    // vector staging: 11 rows x 56 float4 across all 288 threads
    {
        const float4* xb4 = (const float4*)(x + (size_t)bc * ISTR);
        for (unsigned f = tid; f < 616u; f += 288u) {
            unsigned sr = f / 56u;
            unsigned q  = f - 56u * sr;
            int ih = (int)g8 - 1 + (int)sr;
            float4 v = make_float4(0.f, 0.f, 0.f, 0.f);
            if ((unsigned)ih < 224u) v = __ldg(xb4 + (unsigned)ih * 56u + q);
            *((float4*)&sbuf[sr][4] + q) = v;
        }
    }
    __syncthreads();

    unsigned ki = w / 3u;
    unsigned kj = w - 3u * ki;
    unsigned ck = bc * 9u + w;
    unsigned nrows = (g8 + 8u <= 223u) ? 8u : (223u - g8);   // 8, last chunk 7

    for (unsigned r = 0; r < nrows; ++r) {
        unsigned oh   = g8 + r;
        size_t   drow = (size_t)ck * OSP + (size_t)oh * 223u;
        unsigned lead = (4u - ((unsigned)drow & 3u)) & 3u;
        unsigned tail = 3u - lead;
        unsigned sr   = r + ki;
        unsigned off  = lead + kj + 3u;     // padded-row idx of first body float
        unsigned dlt  = off & 3u;
        unsigned jb   = off >> 2u;
        const float4* sm4 = (const float4*)sbuf[sr];
        float4* dst4 = (float4*)(out + drow + lead);

        // 55 fully-in-row aligned float4 stores
        for (unsigned j = lane; j < 55u; j += 32u) {
            float4 a = sm4[jb + j];
            float4 b = sm4[jb + j + 1u];
            float4 v;
            switch (dlt) {
              case 0:  v = a; break;
              case 1:  v = make_float4(a.y, a.z, a.w, b.x); break;
              case 2:  v = make_float4(a.z, a.w, b.x, b.y); break;
              default: v = make_float4(a.w, b.x, b.y, b.z); break;
            }
            __stcs(dst4 + j, v);
        }

        // straddle float4 across row boundary (tail of oh + lead of oh+1)
        if (lane == 0u && tail != 0u && oh < 222u) {
            float vv[4];
#pragma unroll
            for (unsigned t = 0; t < 4u; ++t) {
                vv[t] = (t < tail) ? sbuf[sr][off + 220u + t]
                                   : sbuf[sr + 1u][(t - tail) + kj + 3u];
            }
            __stcs((float4*)(out + drow + lead + 220u),
                   make_float4(vv[0], vv[1], vv[2], vv[3]));
        }

        // plane-end tail scalars (oh == 222 only)
        if (oh == 222u && lane < tail) {
            __stcs(out + drow + lead + 220u + lane, sbuf[sr][off + 220u + lane]);
        }

        // plane-start head scalars (first chunk, first row only)
        if (g8 == 0u && r == 0u && lane < lead) {
            __stcs(out + drow + lane, sbuf[sr][lane + kj + 3u]);
        }
    }
}

extern "C" void kernel_launch(void* const* d_in, const int* in_sizes, int n_in,
                              void* d_out, int out_size) {
    const float* x = (const float*)d_in[0];
    float* out = (float*)d_out;
    dim3 grid(28, 256);   // 28 row-groups (27*8 + 7), 256 bc planes
    unfold_v10<<<grid, 288>>>(x, out);
}

// round 11
// speedup vs baseline: 1.3668x; 1.0008x over previous
#include <cuda_runtime.h>
#include <stdint.h>

// IN:  x (4, 64, 224, 224) fp32
// OUT: (4, 576, 223*223) fp32, plane ck = bc*9 + ki*3 + kj
// out[ck, oh*223+ow] = x[bc, oh+ki-1, ow+kj-1] (0 if OOB)
#define OSP   49729u      // 223*223
#define ISTR  50176u      // 224*224

// Block = (8-row output group, bc). 9 warps = 9 (ki,kj) planes.
// Padded row P = [4 zeros | 224 data | 4 zeros]; two shifted smem copies:
//   sb0[k] = P[k], sb1[k] = P[k+1]  (built in one vectorized staging pass)
// Every output float4 = ONE LDS.128 (dlt 0/1) or TWO aligned LDS.64 (dlt 2/3):
// no second 16B load, no component-select ALU.
__global__ void __launch_bounds__(288, 7) unfold_v11(const float* __restrict__ x,
                                                     float* __restrict__ out) {
    __shared__ __align__(16) float sb0[11][232];
    __shared__ __align__(16) float sb1[11][232];
    unsigned g8  = blockIdx.x * 8u;
    unsigned bc  = blockIdx.y;
    unsigned tid = threadIdx.x;
    unsigned w = tid >> 5, lane = tid & 31u;

    // zero sb0 pads (8 per row x 11 rows)
    if (tid < 88u) {
        unsigned sr = tid >> 3u, p = tid & 7u;
        sb0[sr][p < 4u ? p : 224u + p] = 0.0f;
    }

    // vectorized staging of both copies: 11 rows x 56 float4
    {
        const float4* xb4 = (const float4*)(x + (size_t)bc * ISTR);
#pragma unroll
        for (unsigned it = 0; it < 3u; ++it) {
            unsigned f  = tid + 288u * it;       // < 864; valid if < 616
            unsigned sr = f / 56u;
            unsigned q  = f - 56u * sr;
            int ih = (int)g8 - 1 + (int)sr;
            bool rok = (f < 616u) && ((unsigned)ih < 224u);
            const float4* xr4 = xb4 + (unsigned)(rok ? ih : 0) * 56u;
            float4 v = make_float4(0.f, 0.f, 0.f, 0.f);
            if (rok) v = __ldg(xr4 + q);
            // next f4's .x (warp-internal neighbor); patch lane 31 / row end
            float nx = __shfl_down_sync(0xffffffffu, v.x, 1);
            if (lane == 31u && q < 55u && rok) nx = __ldg((const float*)(xr4 + q + 1u));
            if (q == 55u) nx = 0.0f;             // P[228] = pad
            if (f < 616u) {
                *((float4*)&sb0[sr][4] + q) = v;                    // P[4q+4..+7]
                ((float4*)sb1[sr])[q + 1u] =
                    make_float4(v.y, v.z, v.w, nx);                 // P[4q+5..+8]
                if (q == 0u)
                    ((float4*)sb1[sr])[0] = make_float4(0.f, 0.f, 0.f, v.x); // P[1..4]
            }
        }
    }
    __syncthreads();

    unsigned ki = w / 3u;
    unsigned kj = w - 3u * ki;
    unsigned ck = bc * 9u + w;
    unsigned nrows = (g8 + 8u <= 223u) ? 8u : (223u - g8);   // 8, last chunk 7

    for (unsigned r = 0; r < nrows; ++r) {
        unsigned oh   = g8 + r;
        size_t   drow = (size_t)ck * OSP + (size_t)oh * 223u;
        unsigned lead = (4u - ((unsigned)drow & 3u)) & 3u;
        unsigned tail = 3u - lead;
        unsigned sr   = r + ki;
        unsigned off  = lead + kj + 3u;     // P idx of first body float (3..8)
        unsigned dlt  = off & 3u;
        float4* dst4 = (float4*)(out + drow + lead);

        // 55 aligned float4 stores; value = P[off+4j .. off+4j+3]
        switch (dlt) {
        case 0: {   // one LDS.128 from sb0
            const float4* B = (const float4*)sb0[sr];
            unsigned jb = off >> 2u;
            for (unsigned j = lane; j < 55u; j += 32u)
                __stcs(dst4 + j, B[jb + j]);
        } break;
        case 1: {   // one LDS.128 from sb1
            const float4* B = (const float4*)sb1[sr];
            unsigned jb = (off - 1u) >> 2u;
            for (unsigned j = lane; j < 55u; j += 32u)
                __stcs(dst4 + j, B[jb + j]);
        } break;
        case 2: {   // two LDS.64 from sb0
            const float2* H = (const float2*)sb0[sr];
            unsigned hb = off >> 1u;
            for (unsigned j = lane; j < 55u; j += 32u) {
                float2 a = H[hb + 2u * j];
                float2 b = H[hb + 2u * j + 1u];
                __stcs(dst4 + j, make_float4(a.x, a.y, b.x, b.y));
            }
        } break;
        default: {  // two LDS.64 from sb1
            const float2* H = (const float2*)sb1[sr];
            unsigned hb = (off - 1u) >> 1u;
            for (unsigned j = lane; j < 55u; j += 32u) {
                float2 a = H[hb + 2u * j];
                float2 b = H[hb + 2u * j + 1u];
                __stcs(dst4 + j, make_float4(a.x, a.y, b.x, b.y));
            }
        } break;
        }

        // straddle float4 across row boundary (tail of oh + lead of oh+1)
        if (lane == 0u && tail != 0u && oh < 222u) {
            float vv[4];
#pragma unroll
            for (unsigned t = 0; t < 4u; ++t) {
                vv[t] = (t < tail) ? sb0[sr][off + 220u + t]
                                   : sb0[sr + 1u][(t - tail) + kj + 3u];
            }
            __stcs((float4*)(out + drow + lead + 220u),
                   make_float4(vv[0], vv[1], vv[2], vv[3]));
        }

        // plane-end tail scalars (oh == 222 only)
        if (oh == 222u && lane < tail) {
            __stcs(out + drow + lead + 220u + lane, sb0[sr][off + 220u + lane]);
        }

        // plane-start head scalars (first chunk, first row only)
        if (g8 == 0u && r == 0u && lane < lead) {
            __stcs(out + drow + lane, sb0[sr][lane + kj + 3u]);
        }
    }
}

extern "C" void kernel_launch(void* const* d_in, const int* in_sizes, int n_in,
                              void* d_out, int out_size) {
    const float* x = (const float*)d_in[0];
    float* out = (float*)d_out;
    dim3 grid(28, 256);   // 28 row-groups (27*8 + 7), 256 bc planes
    unfold_v11<<<grid, 288>>>(x, out);
}